// round 6
// baseline (speedup 1.0000x reference)
#include <cuda_runtime.h>
#include <math.h>

#define N_NODES  100000
#define N_EDGES  1000000
#define DIM      64
#define EDIM     32
#define HID      128
#define NLAYERS  4
#define NGRAPHS  64
#define CATDIM   160
#define TABN     4096
#define DRANGE   8.0f
#define ICHUNK   64

typedef unsigned long long u64;

// ---------------- f32x2 packed-math helpers (Blackwell) ----------------
__device__ __forceinline__ u64 pk2(float x, float y) {
    u64 r; asm("mov.b64 %0, {%1,%2};" : "=l"(r) : "f"(x), "f"(y)); return r;
}
__device__ __forceinline__ void upk2(u64 v, float& x, float& y) {
    asm("mov.b64 {%0,%1}, %2;" : "=f"(x), "=f"(y) : "l"(v));
}
__device__ __forceinline__ u64 fma2(u64 a, u64 b, u64 c) {
    u64 d; asm("fma.rn.f32x2 %0, %1, %2, %3;" : "=l"(d) : "l"(a), "l"(b), "l"(c)); return d;
}

// ---------------- device scratch (no allocs allowed) ----------------
__device__ float g_h[N_NODES * DIM];           // 25.6 MB node features
__device__ float g_hd[N_NODES * HID];          // 51.2 MB  h @ W1[0:64] + b1
__device__ float g_hs[N_NODES * HID];          // 51.2 MB  h @ W1[64:128]
__device__ float g_agg[N_NODES * DIM];         // 25.6 MB segment-sum accumulator
__device__ int4  g_epack[N_EDGES];             // 16 MB {src, dst, idx<<1|kind, frac}
__device__ float g_tab[NLAYERS * 2 * TABN * HID]; // 16.8 MB edge-attr projection table
__device__ float g_psum[NGRAPHS * DIM];
__device__ float g_pcnt[NGRAPHS];

// ---------------- kernels ----------------
__global__ void k_zero() {
    int idx = blockIdx.x * blockDim.x + threadIdx.x;
    if (idx < N_NODES * DIM) g_agg[idx] = 0.f;
    if (idx < NGRAPHS * DIM) g_psum[idx] = 0.f;
    if (idx < NGRAPHS)       g_pcnt[idx] = 0.f;
}

__global__ void k_embed(const int* __restrict__ atoms, const float* __restrict__ emb) {
    int idx = blockIdx.x * blockDim.x + threadIdx.x;
    if (idx >= N_NODES * DIM) return;
    int n = idx >> 6, d = idx & 63;
    g_h[idx] = emb[atoms[n] * DIM + d];
}

// tab[l][kind][i][c] = sum_g rbf(d_i,g)*W1e[g][c] + sub[kind]@W1k[:,c]
__global__ void k_tab(const float* __restrict__ W1, const float* __restrict__ sub) {
    __shared__ float sW[32 * HID];
    __shared__ float srbf[16];
    int l  = blockIdx.x / (TABN / ICHUNK);
    int i0 = (blockIdx.x % (TABN / ICHUNK)) * ICHUNK;
    int c  = threadIdx.x;
    const float* W1e = W1 + (size_t)l * CATDIM * HID + (size_t)(2 * DIM) * HID;
    for (int i = c; i < 32 * HID; i += blockDim.x) sW[i] = W1e[i];
    __syncthreads();
    float ks0 = 0.f, ks1 = 0.f;
    #pragma unroll
    for (int j = 0; j < 16; j++) {
        float w = sW[(16 + j) * HID + c];
        ks0 = fmaf(__ldg(&sub[j]),      w, ks0);
        ks1 = fmaf(__ldg(&sub[16 + j]), w, ks1);
    }
    for (int ii = 0; ii < ICHUNK; ii++) {
        int i = i0 + ii;
        float d = (float)i * (DRANGE / (float)(TABN - 1));
        if (c < 16) {
            float t = d - (float)c * (5.0f / 15.0f);
            srbf[c] = __expf(-4.5f * t * t);
        }
        __syncthreads();
        float acc = 0.f;
        #pragma unroll
        for (int g = 0; g < 16; g++) acc = fmaf(srbf[g], sW[g * HID + c], acc);
        size_t base = (((size_t)l * 2) * TABN + i) * HID + c;
        g_tab[base]                      = acc + ks0;
        g_tab[base + (size_t)TABN * HID] = acc + ks1;
        __syncthreads();
    }
}

__global__ void k_pack(const int* __restrict__ ei, const float* __restrict__ coords,
                       const int* __restrict__ isr) {
    int e = blockIdx.x * blockDim.x + threadIdx.x;
    if (e >= N_EDGES) return;
    int s = ei[e], d = ei[N_EDGES + e];
    float dx = coords[3*s]   - coords[3*d];
    float dy = coords[3*s+1] - coords[3*d+1];
    float dz = coords[3*s+2] - coords[3*d+2];
    float dist = sqrtf(dx*dx + dy*dy + dz*dz);
    float u = fminf(dist * ((float)(TABN - 1) / DRANGE), (float)TABN - 1.001f);
    int idx = (int)u;
    float frac = u - (float)idx;
    int kind = (isr[s] != isr[d]) ? 1 : 0;
    g_epack[e] = make_int4(s, d, (idx << 1) | kind, __float_as_int(frac));
}

// hd[n][c] = b1[c] + h[n]@W1[0:64][c] ; hs[n][c] = h[n]@W1[64:128][c]
__global__ void k_node_lin(const float* __restrict__ W1, const float* __restrict__ b1, int layer) {
    extern __shared__ float sm[];
    float* sW1 = sm;            // [128][128]
    float* sh  = sm + HID*HID;  // [4][64]
    const float* W1l = W1 + (size_t)layer * CATDIM * HID;
    for (int i = threadIdx.x; i < HID * HID; i += blockDim.x) sW1[i] = W1l[i];
    int c    = threadIdx.x & 127;
    int half = threadIdx.x >> 7;
    float bias = half ? 0.f : __ldg(&b1[layer * HID + c]);
    float* outbuf = half ? g_hs : g_hd;
    const float* wbase = sW1 + half * (DIM * HID);
    __syncthreads();
    for (int tile = blockIdx.x; tile * 4 < N_NODES; tile += gridDim.x) {
        int base = tile * 4;
        for (int i = threadIdx.x; i < 4 * DIM; i += blockDim.x)
            sh[i] = g_h[base * DIM + i];
        __syncthreads();
        float acc0 = bias, acc1 = bias, acc2 = bias, acc3 = bias;
        #pragma unroll
        for (int k = 0; k < DIM; k += 4) {
            float w0 = wbase[(k + 0) * HID + c];
            float w1 = wbase[(k + 1) * HID + c];
            float w2 = wbase[(k + 2) * HID + c];
            float w3 = wbase[(k + 3) * HID + c];
            float4 a = *(const float4*)&sh[k];
            float4 b = *(const float4*)&sh[64 + k];
            float4 e = *(const float4*)&sh[128 + k];
            float4 f = *(const float4*)&sh[192 + k];
            acc0 = fmaf(a.x, w0, acc0); acc0 = fmaf(a.y, w1, acc0);
            acc0 = fmaf(a.z, w2, acc0); acc0 = fmaf(a.w, w3, acc0);
            acc1 = fmaf(b.x, w0, acc1); acc1 = fmaf(b.y, w1, acc1);
            acc1 = fmaf(b.z, w2, acc1); acc1 = fmaf(b.w, w3, acc1);
            acc2 = fmaf(e.x, w0, acc2); acc2 = fmaf(e.y, w1, acc2);
            acc2 = fmaf(e.z, w2, acc2); acc2 = fmaf(e.w, w3, acc2);
            acc3 = fmaf(f.x, w0, acc3); acc3 = fmaf(f.y, w1, acc3);
            acc3 = fmaf(f.z, w2, acc3); acc3 = fmaf(f.w, w3, acc3);
        }
        outbuf[(size_t)(base + 0) * HID + c] = acc0;
        outbuf[(size_t)(base + 1) * HID + c] = acc1;
        outbuf[(size_t)(base + 2) * HID + c] = acc2;
        outbuf[(size_t)(base + 3) * HID + c] = acc3;
        __syncthreads();
    }
}

// warp per 4-edge batch:
//   pre = hd[dst] + hs[src] + lerp(tab)   -> t = silu(pre)
//   transpose t through smem, then t@W2 with packed f32x2 FMA (2 edges per b64 lane)
//   msg += b2 ; atomic agg at dst
__global__ void k_edge_msg(const float* __restrict__ W2,
                           const float* __restrict__ b2, int layer) {
    extern __shared__ float sm[];
    float4* sW2r = (float4*)sm;               // [128 k][32 lane] = (w[k][d], w[k][d], w[k][d+32], w[k][d+32])
    float*  sT   = sm + 4 * HID * 32;         // per-warp [128 k][4 edge]
    const float* W2l = W2 + (size_t)layer * HID * DIM;
    for (int i = threadIdx.x; i < HID * 32; i += blockDim.x) {
        int k = i >> 5, d = i & 31;
        float a = W2l[k * DIM + d], b = W2l[k * DIM + d + 32];
        sW2r[i] = make_float4(a, a, b, b);
    }
    __syncthreads();
    int lane = threadIdx.x & 31;
    int wIn  = threadIdx.x >> 5;
    float* sTw = sT + wIn * (HID * 4);
    float b2a = __ldg(&b2[layer * DIM + lane]);
    float b2b = __ldg(&b2[layer * DIM + lane + 32]);
    u64 b2a2 = pk2(b2a, b2a);
    u64 b2b2 = pk2(b2b, b2b);
    const float* tabL = g_tab + (size_t)layer * 2 * TABN * HID;
    int warpId = blockIdx.x * (blockDim.x >> 5) + wIn;
    int nW = gridDim.x * (blockDim.x >> 5);
    for (int base = warpId * 4; base < N_EDGES; base += nW * 4) {
        int dstv[4];
        // gather + pre + silu + transposed store into sTw[k][i]
        #pragma unroll
        for (int i = 0; i < 4; i++) {
            int4 ep = g_epack[base + i];
            dstv[i] = ep.y;
            float4 p = *(const float4*)&g_hd[(size_t)ep.y * HID + lane * 4];
            float4 q = *(const float4*)&g_hs[(size_t)ep.x * HID + lane * 4];
            const float* trow = tabL + ((size_t)(ep.z & 1) * TABN + (ep.z >> 1)) * HID + lane * 4;
            float4 t0 = *(const float4*)trow;
            float4 t1 = *(const float4*)(trow + HID);
            float f = __int_as_float(ep.w);
            float x0 = fmaf(f, t1.x - t0.x, p.x + q.x + t0.x);
            float x1 = fmaf(f, t1.y - t0.y, p.y + q.y + t0.y);
            float x2 = fmaf(f, t1.z - t0.z, p.z + q.z + t0.z);
            float x3 = fmaf(f, t1.w - t0.w, p.w + q.w + t0.w);
            // silu
            x0 = __fdividef(x0, 1.0f + __expf(-x0));
            x1 = __fdividef(x1, 1.0f + __expf(-x1));
            x2 = __fdividef(x2, 1.0f + __expf(-x2));
            x3 = __fdividef(x3, 1.0f + __expf(-x3));
            sTw[(lane * 4 + 0) * 4 + i] = x0;
            sTw[(lane * 4 + 1) * 4 + i] = x1;
            sTw[(lane * 4 + 2) * 4 + i] = x2;
            sTw[(lane * 4 + 3) * 4 + i] = x3;
        }
        __syncwarp();
        // t @ W2 : 4 packed accumulators (edges paired in f32x2 lanes)
        u64 acc01l = b2a2, acc01h = b2b2, acc23l = b2a2, acc23h = b2b2;
        const ulonglong2* tq = (const ulonglong2*)sTw;       // [k] -> (t[e0],t[e1]),(t[e2],t[e3])
        const ulonglong2* wq = (const ulonglong2*)(sW2r + lane); // stride 32 float4 per k
        #pragma unroll 8
        for (int k = 0; k < HID; k++) {
            ulonglong2 tv = tq[k];
            ulonglong2 wv = wq[(size_t)k * 32];
            acc01l = fma2(tv.x, wv.x, acc01l);
            acc01h = fma2(tv.x, wv.y, acc01h);
            acc23l = fma2(tv.y, wv.x, acc23l);
            acc23h = fma2(tv.y, wv.y, acc23h);
        }
        float v0, v1;
        upk2(acc01l, v0, v1);
        atomicAdd(&g_agg[(size_t)dstv[0] * DIM + lane], v0);
        atomicAdd(&g_agg[(size_t)dstv[1] * DIM + lane], v1);
        upk2(acc01h, v0, v1);
        atomicAdd(&g_agg[(size_t)dstv[0] * DIM + lane + 32], v0);
        atomicAdd(&g_agg[(size_t)dstv[1] * DIM + lane + 32], v1);
        upk2(acc23l, v0, v1);
        atomicAdd(&g_agg[(size_t)dstv[2] * DIM + lane], v0);
        atomicAdd(&g_agg[(size_t)dstv[3] * DIM + lane], v1);
        upk2(acc23h, v0, v1);
        atomicAdd(&g_agg[(size_t)dstv[2] * DIM + lane + 32], v0);
        atomicAdd(&g_agg[(size_t)dstv[3] * DIM + lane + 32], v1);
        __syncwarp();
    }
}

__global__ void k_update() {  // h = relu(h+agg); re-zero agg
    int idx = blockIdx.x * blockDim.x + threadIdx.x;
    if (idx >= N_NODES * DIM) return;
    float v = g_h[idx] + g_agg[idx];
    g_h[idx] = fmaxf(v, 0.f);
    g_agg[idx] = 0.f;
}

__global__ void k_pool(const int* __restrict__ bids) {
    int idx = blockIdx.x * blockDim.x + threadIdx.x;
    if (idx >= N_NODES * DIM) return;
    int n = idx >> 6, d = idx & 63;
    int b = bids[n];
    atomicAdd(&g_psum[b * DIM + d], g_h[idx]);
    if (d == 0) atomicAdd(&g_pcnt[b], 1.f);
}

__global__ void k_out(const float* __restrict__ fcw, const float* __restrict__ fcb,
                      float* __restrict__ out) {
    int g = threadIdx.x;
    if (g >= NGRAPHS) return;
    float s = 0.f;
    #pragma unroll
    for (int d = 0; d < DIM; d++) s += g_psum[g * DIM + d] * fcw[d];
    out[g] = s / fmaxf(g_pcnt[g], 1.f) + fcb[0];
}

// ---------------- launch ----------------
extern "C" void kernel_launch(void* const* d_in, const int* in_sizes, int n_in,
                              void* d_out, int out_size) {
    const int*   atoms  = (const int*)d_in[0];
    const int*   ei     = (const int*)d_in[1];
    const float* coords = (const float*)d_in[2];
    const int*   isr    = (const int*)d_in[3];
    const int*   bids   = (const int*)d_in[4];
    const float* emb    = (const float*)d_in[5];
    const float* sub    = (const float*)d_in[6];
    const float* W1     = (const float*)d_in[7];
    const float* b1     = (const float*)d_in[8];
    const float* W2     = (const float*)d_in[9];
    const float* b2     = (const float*)d_in[10];
    const float* fcw    = (const float*)d_in[11];
    const float* fcb    = (const float*)d_in[12];
    float* out = (float*)d_out;

    const int NL_SMEM = (HID * HID + 4 * DIM) * (int)sizeof(float);            // 66560 B
    const int EM_SMEM = (4 * HID * 32 + 8 * HID * 4) * (int)sizeof(float);     // 65536+16384 = 81920 B
    cudaFuncSetAttribute(k_node_lin, cudaFuncAttributeMaxDynamicSharedMemorySize, NL_SMEM);
    cudaFuncSetAttribute(k_edge_msg, cudaFuncAttributeMaxDynamicSharedMemorySize, EM_SMEM);

    k_zero<<<25000, 256>>>();
    k_embed<<<25000, 256>>>(atoms, emb);
    k_tab<<<NLAYERS * (TABN / ICHUNK), 128>>>(W1, sub);
    k_pack<<<(N_EDGES + 255) / 256, 256>>>(ei, coords, isr);
    for (int l = 0; l < NLAYERS; l++) {
        k_node_lin<<<1250, 256, NL_SMEM>>>(W1, b1, l);
        k_edge_msg<<<1184, 256, EM_SMEM>>>(W2, b2, l);
        k_update<<<25000, 256>>>();
    }
    k_pool<<<25000, 256>>>(bids);
    k_out<<<1, 64>>>(fcw, fcb, out);
}

// round 8
// speedup vs baseline: 1.3517x; 1.3517x over previous
#include <cuda_runtime.h>
#include <math.h>

#define N_NODES  100000
#define N_EDGES  1000000
#define DIM      64
#define EDIM     32
#define HID      128
#define NLAYERS  4
#define NGRAPHS  64
#define CATDIM   160
#define TABN     4096
#define DRANGE   8.0f
#define ICHUNK   64

typedef unsigned long long u64;

// ---------------- f32x2 packed-math helpers (Blackwell) ----------------
__device__ __forceinline__ void upk2(u64 v, float& x, float& y) {
    asm("mov.b64 {%0,%1}, %2;" : "=f"(x), "=f"(y) : "l"(v));
}
__device__ __forceinline__ u64 fma2(u64 a, u64 b, u64 c) {
    u64 d; asm("fma.rn.f32x2 %0, %1, %2, %3;" : "=l"(d) : "l"(a), "l"(b), "l"(c)); return d;
}

// ---------------- device scratch (no allocs allowed) ----------------
__device__ float g_h[N_NODES * DIM];           // 25.6 MB node features
__device__ float g_hd[N_NODES * HID];          // 51.2 MB  h @ W1[0:64] + b1
__device__ float g_hs[N_NODES * HID];          // 51.2 MB  h @ W1[64:128]
__device__ float g_agg[N_NODES * DIM];         // 25.6 MB segment-sum accumulator
__device__ int4  g_epack[N_EDGES];             // 16 MB {src, dst, idx<<1|kind, frac}
__device__ float g_tab[NLAYERS * 2 * TABN * HID]; // 16.8 MB edge-attr projection table
__device__ float g_psum[NGRAPHS * DIM];
__device__ float g_pcnt[NGRAPHS];

// ---------------- kernels ----------------
__global__ void k_zero() {
    int idx = blockIdx.x * blockDim.x + threadIdx.x;
    if (idx < N_NODES * DIM) g_agg[idx] = 0.f;
    if (idx < NGRAPHS * DIM) g_psum[idx] = 0.f;
    if (idx < NGRAPHS)       g_pcnt[idx] = 0.f;
}

__global__ void k_embed(const int* __restrict__ atoms, const float* __restrict__ emb) {
    int idx = blockIdx.x * blockDim.x + threadIdx.x;
    if (idx >= N_NODES * DIM) return;
    int n = idx >> 6, d = idx & 63;
    g_h[idx] = emb[atoms[n] * DIM + d];
}

// tab[l][kind][i][c] = sum_g rbf(d_i,g)*W1e[g][c] + sub[kind]@W1k[:,c]
__global__ void k_tab(const float* __restrict__ W1, const float* __restrict__ sub) {
    __shared__ float sW[32 * HID];
    __shared__ float srbf[16];
    int l  = blockIdx.x / (TABN / ICHUNK);
    int i0 = (blockIdx.x % (TABN / ICHUNK)) * ICHUNK;
    int c  = threadIdx.x;
    const float* W1e = W1 + (size_t)l * CATDIM * HID + (size_t)(2 * DIM) * HID;
    for (int i = c; i < 32 * HID; i += blockDim.x) sW[i] = W1e[i];
    __syncthreads();
    float ks0 = 0.f, ks1 = 0.f;
    #pragma unroll
    for (int j = 0; j < 16; j++) {
        float w = sW[(16 + j) * HID + c];
        ks0 = fmaf(__ldg(&sub[j]),      w, ks0);
        ks1 = fmaf(__ldg(&sub[16 + j]), w, ks1);
    }
    for (int ii = 0; ii < ICHUNK; ii++) {
        int i = i0 + ii;
        float d = (float)i * (DRANGE / (float)(TABN - 1));
        if (c < 16) {
            float t = d - (float)c * (5.0f / 15.0f);
            srbf[c] = __expf(-4.5f * t * t);
        }
        __syncthreads();
        float acc = 0.f;
        #pragma unroll
        for (int g = 0; g < 16; g++) acc = fmaf(srbf[g], sW[g * HID + c], acc);
        size_t base = (((size_t)l * 2) * TABN + i) * HID + c;
        g_tab[base]                      = acc + ks0;
        g_tab[base + (size_t)TABN * HID] = acc + ks1;
        __syncthreads();
    }
}

__global__ void k_pack(const int* __restrict__ ei, const float* __restrict__ coords,
                       const int* __restrict__ isr) {
    int e = blockIdx.x * blockDim.x + threadIdx.x;
    if (e >= N_EDGES) return;
    int s = ei[e], d = ei[N_EDGES + e];
    float dx = coords[3*s]   - coords[3*d];
    float dy = coords[3*s+1] - coords[3*d+1];
    float dz = coords[3*s+2] - coords[3*d+2];
    float dist = sqrtf(dx*dx + dy*dy + dz*dz);
    float u = fminf(dist * ((float)(TABN - 1) / DRANGE), (float)TABN - 1.001f);
    int idx = (int)u;
    float frac = u - (float)idx;
    int kind = (isr[s] != isr[d]) ? 1 : 0;
    g_epack[e] = make_int4(s, d, (idx << 1) | kind, __float_as_int(frac));
}

// hd[n][c] = b1[c] + h[n]@W1[0:64][c] ; hs[n][c] = h[n]@W1[64:128][c]
// W1 transposed into per-thread rows sWt[tid][68] so weight reads are LDS.128.
__global__ void k_node_lin(const float* __restrict__ W1, const float* __restrict__ b1, int layer) {
    extern __shared__ float sm[];
    float* sWt = sm;              // [256][68] (64 weights + 4 pad per thread)
    float* sh  = sm + 256 * 68;   // [4][64]
    const float* W1l = W1 + (size_t)layer * CATDIM * HID;
    for (int i = threadIdx.x; i < HID * HID; i += blockDim.x) {
        int r = i >> 7, c = i & 127;
        int t = ((r >> 6) << 7) + c;      // owner thread = half*128 + c
        sWt[t * 68 + (r & 63)] = W1l[i];
    }
    int c    = threadIdx.x & 127;
    int half = threadIdx.x >> 7;
    float bias = half ? 0.f : __ldg(&b1[layer * HID + c]);
    float* outbuf = half ? g_hs : g_hd;
    const float* wp = sWt + threadIdx.x * 68;
    __syncthreads();
    for (int tile = blockIdx.x; tile * 4 < N_NODES; tile += gridDim.x) {
        int base = tile * 4;
        for (int i = threadIdx.x; i < 4 * DIM; i += blockDim.x)
            sh[i] = g_h[base * DIM + i];
        __syncthreads();
        float acc0 = bias, acc1 = bias, acc2 = bias, acc3 = bias;
        #pragma unroll
        for (int k = 0; k < DIM; k += 4) {
            float4 w = *(const float4*)&wp[k];
            float4 a = *(const float4*)&sh[k];
            float4 b = *(const float4*)&sh[64 + k];
            float4 e = *(const float4*)&sh[128 + k];
            float4 f = *(const float4*)&sh[192 + k];
            acc0 = fmaf(a.x, w.x, acc0); acc0 = fmaf(a.y, w.y, acc0);
            acc0 = fmaf(a.z, w.z, acc0); acc0 = fmaf(a.w, w.w, acc0);
            acc1 = fmaf(b.x, w.x, acc1); acc1 = fmaf(b.y, w.y, acc1);
            acc1 = fmaf(b.z, w.z, acc1); acc1 = fmaf(b.w, w.w, acc1);
            acc2 = fmaf(e.x, w.x, acc2); acc2 = fmaf(e.y, w.y, acc2);
            acc2 = fmaf(e.z, w.z, acc2); acc2 = fmaf(e.w, w.w, acc2);
            acc3 = fmaf(f.x, w.x, acc3); acc3 = fmaf(f.y, w.y, acc3);
            acc3 = fmaf(f.z, w.z, acc3); acc3 = fmaf(f.w, w.w, acc3);
        }
        outbuf[(size_t)(base + 0) * HID + c] = acc0;
        outbuf[(size_t)(base + 1) * HID + c] = acc1;
        outbuf[(size_t)(base + 2) * HID + c] = acc2;
        outbuf[(size_t)(base + 3) * HID + c] = acc3;
        __syncthreads();
    }
}

// warp per 4-edge batch:
//   pre = hd[dst] + hs[src] + lerp(tab) -> t = silu(pre), staged edge-major in smem
//   t@W2 with f32x2: even/odd k partial sums in the two b64 halves, broadcast LDS.64
//   for t pairs, LDS.128 for (even,odd)x(d,d+32) weights. No shfl, no bank conflicts.
__global__ void k_edge_msg(const float* __restrict__ W2,
                           const float* __restrict__ b2, int layer) {
    extern __shared__ float sm[];
    float4* sW2t = (float4*)sm;            // [64 pair][32 lane]: (w[2p][d], w[2p+1][d], w[2p][d+32], w[2p+1][d+32])
    float*  sT   = sm + 4 * 64 * 32;       // per-warp [4 edge][128 k]
    const float* W2l = W2 + (size_t)layer * HID * DIM;
    for (int i = threadIdx.x; i < 64 * 32; i += blockDim.x) {
        int p = i >> 5, d = i & 31;
        sW2t[i] = make_float4(W2l[(2*p) * DIM + d],      W2l[(2*p+1) * DIM + d],
                              W2l[(2*p) * DIM + d + 32], W2l[(2*p+1) * DIM + d + 32]);
    }
    __syncthreads();
    int lane = threadIdx.x & 31;
    int wIn  = threadIdx.x >> 5;
    float* sTw = sT + wIn * (4 * HID);
    float b2a = __ldg(&b2[layer * DIM + lane]);
    float b2b = __ldg(&b2[layer * DIM + lane + 32]);
    const float* tabL = g_tab + (size_t)layer * 2 * TABN * HID;
    const ulonglong2* wq = (const ulonglong2*)sW2t;
    int warpId = blockIdx.x * (blockDim.x >> 5) + wIn;
    int nW = gridDim.x * (blockDim.x >> 5);
    for (int base = warpId * 4; base < N_EDGES; base += nW * 4) {
        int dstv[4];
        // gather + pre + silu; store edge-major (STS.128, conflict-free)
        #pragma unroll
        for (int i = 0; i < 4; i++) {
            int4 ep = g_epack[base + i];
            dstv[i] = ep.y;
            float4 p = *(const float4*)&g_hd[(size_t)ep.y * HID + lane * 4];
            float4 q = *(const float4*)&g_hs[(size_t)ep.x * HID + lane * 4];
            const float* trow = tabL + ((size_t)(ep.z & 1) * TABN + (ep.z >> 1)) * HID + lane * 4;
            float4 t0 = *(const float4*)trow;
            float4 t1 = *(const float4*)(trow + HID);
            float f = __int_as_float(ep.w);
            float x0 = fmaf(f, t1.x - t0.x, p.x + q.x + t0.x);
            float x1 = fmaf(f, t1.y - t0.y, p.y + q.y + t0.y);
            float x2 = fmaf(f, t1.z - t0.z, p.z + q.z + t0.z);
            float x3 = fmaf(f, t1.w - t0.w, p.w + q.w + t0.w);
            x0 = __fdividef(x0, 1.0f + __expf(-x0));
            x1 = __fdividef(x1, 1.0f + __expf(-x1));
            x2 = __fdividef(x2, 1.0f + __expf(-x2));
            x3 = __fdividef(x3, 1.0f + __expf(-x3));
            *(float4*)&sTw[i * HID + lane * 4] = make_float4(x0, x1, x2, x3);
        }
        __syncwarp();
        // t @ W2 : even/odd-k partial sums packed in f32x2
        u64 accLo[4] = {0ULL, 0ULL, 0ULL, 0ULL};
        u64 accHi[4] = {0ULL, 0ULL, 0ULL, 0ULL};
        #pragma unroll 8
        for (int p = 0; p < 64; p++) {
            ulonglong2 wv = wq[p * 32 + lane];
            #pragma unroll
            for (int i = 0; i < 4; i++) {
                u64 tv = *(const u64*)&sTw[i * HID + 2 * p];  // broadcast
                accLo[i] = fma2(tv, wv.x, accLo[i]);
                accHi[i] = fma2(tv, wv.y, accHi[i]);
            }
        }
        __syncwarp();
        #pragma unroll
        for (int i = 0; i < 4; i++) {
            float e0, e1;
            upk2(accLo[i], e0, e1);
            atomicAdd(&g_agg[(size_t)dstv[i] * DIM + lane],      b2a + e0 + e1);
            upk2(accHi[i], e0, e1);
            atomicAdd(&g_agg[(size_t)dstv[i] * DIM + lane + 32], b2b + e0 + e1);
        }
    }
}

__global__ void k_update() {  // h = relu(h+agg); re-zero agg
    int idx = blockIdx.x * blockDim.x + threadIdx.x;
    if (idx >= N_NODES * DIM) return;
    float v = g_h[idx] + g_agg[idx];
    g_h[idx] = fmaxf(v, 0.f);
    g_agg[idx] = 0.f;
}

__global__ void k_pool(const int* __restrict__ bids) {
    int idx = blockIdx.x * blockDim.x + threadIdx.x;
    if (idx >= N_NODES * DIM) return;
    int n = idx >> 6, d = idx & 63;
    int b = bids[n];
    atomicAdd(&g_psum[b * DIM + d], g_h[idx]);
    if (d == 0) atomicAdd(&g_pcnt[b], 1.f);
}

__global__ void k_out(const float* __restrict__ fcw, const float* __restrict__ fcb,
                      float* __restrict__ out) {
    int g = threadIdx.x;
    if (g >= NGRAPHS) return;
    float s = 0.f;
    #pragma unroll
    for (int d = 0; d < DIM; d++) s += g_psum[g * DIM + d] * fcw[d];
    out[g] = s / fmaxf(g_pcnt[g], 1.f) + fcb[0];
}

// ---------------- launch ----------------
extern "C" void kernel_launch(void* const* d_in, const int* in_sizes, int n_in,
                              void* d_out, int out_size) {
    const int*   atoms  = (const int*)d_in[0];
    const int*   ei     = (const int*)d_in[1];
    const float* coords = (const float*)d_in[2];
    const int*   isr    = (const int*)d_in[3];
    const int*   bids   = (const int*)d_in[4];
    const float* emb    = (const float*)d_in[5];
    const float* sub    = (const float*)d_in[6];
    const float* W1     = (const float*)d_in[7];
    const float* b1     = (const float*)d_in[8];
    const float* W2     = (const float*)d_in[9];
    const float* b2     = (const float*)d_in[10];
    const float* fcw    = (const float*)d_in[11];
    const float* fcb    = (const float*)d_in[12];
    float* out = (float*)d_out;

    const int NL_SMEM = (256 * 68 + 4 * DIM) * (int)sizeof(float);          // 70656 B
    const int EM_SMEM = (4 * 64 * 32 + 8 * 4 * HID) * (int)sizeof(float);   // 32768+16384 = 49152 B
    cudaFuncSetAttribute(k_node_lin, cudaFuncAttributeMaxDynamicSharedMemorySize, NL_SMEM);
    cudaFuncSetAttribute(k_edge_msg, cudaFuncAttributeMaxDynamicSharedMemorySize, EM_SMEM);

    k_zero<<<25000, 256>>>();
    k_embed<<<25000, 256>>>(atoms, emb);
    k_tab<<<NLAYERS * (TABN / ICHUNK), 128>>>(W1, sub);
    k_pack<<<(N_EDGES + 255) / 256, 256>>>(ei, coords, isr);
    for (int l = 0; l < NLAYERS; l++) {
        k_node_lin<<<1250, 256, NL_SMEM>>>(W1, b1, l);
        k_edge_msg<<<1184, 256, EM_SMEM>>>(W2, b2, l);
        k_update<<<25000, 256>>>();
    }
    k_pool<<<25000, 256>>>(bids);
    k_out<<<1, 64>>>(fcw, fcb, out);
}

// round 13
// speedup vs baseline: 1.4416x; 1.0665x over previous
#include <cuda_runtime.h>
#include <math.h>

#define N_NODES  100000
#define N_EDGES  1000000
#define DIM      64
#define EDIM     32
#define HID      128
#define NLAYERS  4
#define NGRAPHS  64
#define CATDIM   160
#define TABN     4096
#define DRANGE   8.0f
#define ICHUNK   64
#define EB       8      // edges per warp batch

typedef unsigned long long u64;

// ---------------- f32x2 packed-math helpers (Blackwell) ----------------
__device__ __forceinline__ void upk2(u64 v, float& x, float& y) {
    asm("mov.b64 {%0,%1}, %2;" : "=f"(x), "=f"(y) : "l"(v));
}
__device__ __forceinline__ u64 fma2(u64 a, u64 b, u64 c) {
    u64 d; asm("fma.rn.f32x2 %0, %1, %2, %3;" : "=l"(d) : "l"(a), "l"(b), "l"(c)); return d;
}

// ---------------- device scratch (no allocs allowed) ----------------
__device__ float g_h[N_NODES * DIM];           // 25.6 MB node features
__device__ float g_hd[N_NODES * HID];          // 51.2 MB  h @ W1[0:64] + b1
__device__ float g_hs[N_NODES * HID];          // 51.2 MB  h @ W1[64:128]
__device__ float g_agg[N_NODES * DIM];         // 25.6 MB segment-sum accumulator
__device__ int4  g_epack[N_EDGES];             // 16 MB {src, dst, idx<<1|kind, frac}
__device__ float g_tab[NLAYERS * 2 * TABN * HID]; // 16.8 MB edge-attr projection table
__device__ float g_psum[NGRAPHS * DIM];
__device__ float g_pcnt[NGRAPHS];

// ---------------- kernels ----------------
__global__ void k_zero() {
    int idx = blockIdx.x * blockDim.x + threadIdx.x;
    if (idx < N_NODES * DIM) g_agg[idx] = 0.f;
    if (idx < NGRAPHS * DIM) g_psum[idx] = 0.f;
    if (idx < NGRAPHS)       g_pcnt[idx] = 0.f;
}

__global__ void k_embed(const int* __restrict__ atoms, const float* __restrict__ emb) {
    int idx = blockIdx.x * blockDim.x + threadIdx.x;
    if (idx >= N_NODES * DIM) return;
    int n = idx >> 6, d = idx & 63;
    g_h[idx] = emb[atoms[n] * DIM + d];
}

// tab[l][kind][i][c] = sum_g rbf(d_i,g)*W1e[g][c] + sub[kind]@W1k[:,c]
__global__ void k_tab(const float* __restrict__ W1, const float* __restrict__ sub) {
    __shared__ float sW[32 * HID];
    __shared__ float srbf[16];
    int l  = blockIdx.x / (TABN / ICHUNK);
    int i0 = (blockIdx.x % (TABN / ICHUNK)) * ICHUNK;
    int c  = threadIdx.x;
    const float* W1e = W1 + (size_t)l * CATDIM * HID + (size_t)(2 * DIM) * HID;
    for (int i = c; i < 32 * HID; i += blockDim.x) sW[i] = W1e[i];
    __syncthreads();
    float ks0 = 0.f, ks1 = 0.f;
    #pragma unroll
    for (int j = 0; j < 16; j++) {
        float w = sW[(16 + j) * HID + c];
        ks0 = fmaf(__ldg(&sub[j]),      w, ks0);
        ks1 = fmaf(__ldg(&sub[16 + j]), w, ks1);
    }
    for (int ii = 0; ii < ICHUNK; ii++) {
        int i = i0 + ii;
        float d = (float)i * (DRANGE / (float)(TABN - 1));
        if (c < 16) {
            float t = d - (float)c * (5.0f / 15.0f);
            srbf[c] = __expf(-4.5f * t * t);
        }
        __syncthreads();
        float acc = 0.f;
        #pragma unroll
        for (int g = 0; g < 16; g++) acc = fmaf(srbf[g], sW[g * HID + c], acc);
        size_t base = (((size_t)l * 2) * TABN + i) * HID + c;
        g_tab[base]                      = acc + ks0;
        g_tab[base + (size_t)TABN * HID] = acc + ks1;
        __syncthreads();
    }
}

__global__ void k_pack(const int* __restrict__ ei, const float* __restrict__ coords,
                       const int* __restrict__ isr) {
    int e = blockIdx.x * blockDim.x + threadIdx.x;
    if (e >= N_EDGES) return;
    int s = ei[e], d = ei[N_EDGES + e];
    float dx = coords[3*s]   - coords[3*d];
    float dy = coords[3*s+1] - coords[3*d+1];
    float dz = coords[3*s+2] - coords[3*d+2];
    float dist = sqrtf(dx*dx + dy*dy + dz*dz);
    float u = fminf(dist * ((float)(TABN - 1) / DRANGE), (float)TABN - 1.001f);
    int idx = (int)u;
    float frac = u - (float)idx;
    int kind = (isr[s] != isr[d]) ? 1 : 0;
    g_epack[e] = make_int4(s, d, (idx << 1) | kind, __float_as_int(frac));
}

// hd[n][c] = b1[c] + h[n]@W1[0:64][c] ; hs[n][c] = h[n]@W1[64:128][c]
// W1 transposed into per-thread rows sWt[tid][68] so weight reads are LDS.128.
__global__ void k_node_lin(const float* __restrict__ W1, const float* __restrict__ b1, int layer) {
    extern __shared__ float sm[];
    float* sWt = sm;              // [256][68]
    float* sh  = sm + 256 * 68;   // [4][64]
    const float* W1l = W1 + (size_t)layer * CATDIM * HID;
    for (int i = threadIdx.x; i < HID * HID; i += blockDim.x) {
        int r = i >> 7, c = i & 127;
        int t = ((r >> 6) << 7) + c;
        sWt[t * 68 + (r & 63)] = W1l[i];
    }
    int c    = threadIdx.x & 127;
    int half = threadIdx.x >> 7;
    float bias = half ? 0.f : __ldg(&b1[layer * HID + c]);
    float* outbuf = half ? g_hs : g_hd;
    const float* wp = sWt + threadIdx.x * 68;
    __syncthreads();
    for (int tile = blockIdx.x; tile * 4 < N_NODES; tile += gridDim.x) {
        int base = tile * 4;
        for (int i = threadIdx.x; i < 4 * DIM; i += blockDim.x)
            sh[i] = g_h[base * DIM + i];
        __syncthreads();
        float acc0 = bias, acc1 = bias, acc2 = bias, acc3 = bias;
        #pragma unroll
        for (int k = 0; k < DIM; k += 4) {
            float4 w = *(const float4*)&wp[k];
            float4 a = *(const float4*)&sh[k];
            float4 b = *(const float4*)&sh[64 + k];
            float4 e = *(const float4*)&sh[128 + k];
            float4 f = *(const float4*)&sh[192 + k];
            acc0 = fmaf(a.x, w.x, acc0); acc0 = fmaf(a.y, w.y, acc0);
            acc0 = fmaf(a.z, w.z, acc0); acc0 = fmaf(a.w, w.w, acc0);
            acc1 = fmaf(b.x, w.x, acc1); acc1 = fmaf(b.y, w.y, acc1);
            acc1 = fmaf(b.z, w.z, acc1); acc1 = fmaf(b.w, w.w, acc1);
            acc2 = fmaf(e.x, w.x, acc2); acc2 = fmaf(e.y, w.y, acc2);
            acc2 = fmaf(e.z, w.z, acc2); acc2 = fmaf(e.w, w.w, acc2);
            acc3 = fmaf(f.x, w.x, acc3); acc3 = fmaf(f.y, w.y, acc3);
            acc3 = fmaf(f.z, w.z, acc3); acc3 = fmaf(f.w, w.w, acc3);
        }
        outbuf[(size_t)(base + 0) * HID + c] = acc0;
        outbuf[(size_t)(base + 1) * HID + c] = acc1;
        outbuf[(size_t)(base + 2) * HID + c] = acc2;
        outbuf[(size_t)(base + 3) * HID + c] = acc3;
        __syncthreads();
    }
}

// warp per 8-edge batch:
//   pre = hd[dst] + hs[src] + lerp(tab) -> t = silu(pre), staged edge-major in smem
//   t@W2 with f32x2: even/odd k partials in the b64 halves.
//   Per quad q (4 k's = 2 pairs): 2 weight LDS.128 amortized over 8 edges,
//   t via one broadcast LDS.128 per edge. Crossbar ~matched to FFMA2 floor.
__global__ void __launch_bounds__(256, 2) k_edge_msg(const float* __restrict__ W2,
                           const float* __restrict__ b2, int layer) {
    extern __shared__ float sm[];
    float4* sW2t = (float4*)sm;            // [64 pair][32 lane]: (w[2p][d], w[2p+1][d], w[2p][d+32], w[2p+1][d+32])
    float*  sT   = sm + 4 * 64 * 32;       // per-warp [EB edge][128 k]
    const float* W2l = W2 + (size_t)layer * HID * DIM;
    for (int i = threadIdx.x; i < 64 * 32; i += blockDim.x) {
        int p = i >> 5, d = i & 31;
        sW2t[i] = make_float4(W2l[(2*p) * DIM + d],      W2l[(2*p+1) * DIM + d],
                              W2l[(2*p) * DIM + d + 32], W2l[(2*p+1) * DIM + d + 32]);
    }
    __syncthreads();
    int lane = threadIdx.x & 31;
    int wIn  = threadIdx.x >> 5;
    float* sTw = sT + wIn * (EB * HID);
    float b2a = __ldg(&b2[layer * DIM + lane]);
    float b2b = __ldg(&b2[layer * DIM + lane + 32]);
    const float* tabL = g_tab + (size_t)layer * 2 * TABN * HID;
    const ulonglong2* wq = (const ulonglong2*)sW2t;
    int warpId = blockIdx.x * (blockDim.x >> 5) + wIn;
    int nW = gridDim.x * (blockDim.x >> 5);
    for (int base = warpId * EB; base < N_EDGES; base += nW * EB) {
        int dstv[EB];
        // gather + pre + silu; store edge-major (STS.128, conflict-free)
        #pragma unroll
        for (int i = 0; i < EB; i++) {
            int4 ep = g_epack[base + i];
            dstv[i] = ep.y;
            float4 p = *(const float4*)&g_hd[(size_t)ep.y * HID + lane * 4];
            float4 q = *(const float4*)&g_hs[(size_t)ep.x * HID + lane * 4];
            const float* trow = tabL + ((size_t)(ep.z & 1) * TABN + (ep.z >> 1)) * HID + lane * 4;
            float4 t0 = *(const float4*)trow;
            float4 t1 = *(const float4*)(trow + HID);
            float f = __int_as_float(ep.w);
            float x0 = fmaf(f, t1.x - t0.x, p.x + q.x + t0.x);
            float x1 = fmaf(f, t1.y - t0.y, p.y + q.y + t0.y);
            float x2 = fmaf(f, t1.z - t0.z, p.z + q.z + t0.z);
            float x3 = fmaf(f, t1.w - t0.w, p.w + q.w + t0.w);
            x0 = __fdividef(x0, 1.0f + __expf(-x0));
            x1 = __fdividef(x1, 1.0f + __expf(-x1));
            x2 = __fdividef(x2, 1.0f + __expf(-x2));
            x3 = __fdividef(x3, 1.0f + __expf(-x3));
            *(float4*)&sTw[i * HID + lane * 4] = make_float4(x0, x1, x2, x3);
        }
        __syncwarp();
        // t @ W2 : even/odd-k partial sums packed in f32x2
        u64 accLo[EB], accHi[EB];
        #pragma unroll
        for (int i = 0; i < EB; i++) { accLo[i] = 0ULL; accHi[i] = 0ULL; }
        #pragma unroll 4
        for (int q = 0; q < 32; q++) {         // quad = 4 k values = pairs 2q, 2q+1
            ulonglong2 w0 = wq[(2 * q)     * 32 + lane];
            ulonglong2 w1 = wq[(2 * q + 1) * 32 + lane];
            #pragma unroll
            for (int i = 0; i < EB; i++) {
                ulonglong2 tv = *(const ulonglong2*)&sTw[i * HID + 4 * q];  // broadcast LDS.128
                accLo[i] = fma2(tv.x, w0.x, accLo[i]);
                accHi[i] = fma2(tv.x, w0.y, accHi[i]);
                accLo[i] = fma2(tv.y, w1.x, accLo[i]);
                accHi[i] = fma2(tv.y, w1.y, accHi[i]);
            }
        }
        __syncwarp();
        #pragma unroll
        for (int i = 0; i < EB; i++) {
            float e0, e1;
            upk2(accLo[i], e0, e1);
            atomicAdd(&g_agg[(size_t)dstv[i] * DIM + lane],      b2a + e0 + e1);
            upk2(accHi[i], e0, e1);
            atomicAdd(&g_agg[(size_t)dstv[i] * DIM + lane + 32], b2b + e0 + e1);
        }
    }
}

__global__ void k_update() {  // h = relu(h+agg); re-zero agg
    int idx = blockIdx.x * blockDim.x + threadIdx.x;
    if (idx >= N_NODES * DIM) return;
    float v = g_h[idx] + g_agg[idx];
    g_h[idx] = fmaxf(v, 0.f);
    g_agg[idx] = 0.f;
}

__global__ void k_pool(const int* __restrict__ bids) {
    int idx = blockIdx.x * blockDim.x + threadIdx.x;
    if (idx >= N_NODES * DIM) return;
    int n = idx >> 6, d = idx & 63;
    int b = bids[n];
    atomicAdd(&g_psum[b * DIM + d], g_h[idx]);
    if (d == 0) atomicAdd(&g_pcnt[b], 1.f);
}

__global__ void k_out(const float* __restrict__ fcw, const float* __restrict__ fcb,
                      float* __restrict__ out) {
    int g = threadIdx.x;
    if (g >= NGRAPHS) return;
    float s = 0.f;
    #pragma unroll
    for (int d = 0; d < DIM; d++) s += g_psum[g * DIM + d] * fcw[d];
    out[g] = s / fmaxf(g_pcnt[g], 1.f) + fcb[0];
}

// ---------------- launch ----------------
extern "C" void kernel_launch(void* const* d_in, const int* in_sizes, int n_in,
                              void* d_out, int out_size) {
    const int*   atoms  = (const int*)d_in[0];
    const int*   ei     = (const int*)d_in[1];
    const float* coords = (const float*)d_in[2];
    const int*   isr    = (const int*)d_in[3];
    const int*   bids   = (const int*)d_in[4];
    const float* emb    = (const float*)d_in[5];
    const float* sub    = (const float*)d_in[6];
    const float* W1     = (const float*)d_in[7];
    const float* b1     = (const float*)d_in[8];
    const float* W2     = (const float*)d_in[9];
    const float* b2     = (const float*)d_in[10];
    const float* fcw    = (const float*)d_in[11];
    const float* fcb    = (const float*)d_in[12];
    float* out = (float*)d_out;

    const int NL_SMEM = (256 * 68 + 4 * DIM) * (int)sizeof(float);             // 70656 B
    const int EM_SMEM = (4 * 64 * 32 + 8 * EB * HID) * (int)sizeof(float);     // 32768+32768 = 65536 B
    cudaFuncSetAttribute(k_node_lin, cudaFuncAttributeMaxDynamicSharedMemorySize, NL_SMEM);
    cudaFuncSetAttribute(k_edge_msg, cudaFuncAttributeMaxDynamicSharedMemorySize, EM_SMEM);

    k_zero<<<25000, 256>>>();
    k_embed<<<25000, 256>>>(atoms, emb);
    k_tab<<<NLAYERS * (TABN / ICHUNK), 128>>>(W1, sub);
    k_pack<<<(N_EDGES + 255) / 256, 256>>>(ei, coords, isr);
    for (int l = 0; l < NLAYERS; l++) {
        k_node_lin<<<1250, 256, NL_SMEM>>>(W1, b1, l);
        k_edge_msg<<<296, 256, EM_SMEM>>>(W2, b2, l);
        k_update<<<25000, 256>>>();
    }
    k_pool<<<25000, 256>>>(bids);
    k_out<<<1, 64>>>(fcw, fcb, out);
}